// round 10
// baseline (speedup 1.0000x reference)
#include <cuda_runtime.h>
#include <cuda_fp16.h>
#include <float.h>
#include <stdint.h>

// ============================ problem constants ============================
#define KCODES   4096
#define DIMS     256
#define NROWS    32768
#define ZELEMS   8388608
#define LOSS_OFF 8388608
#define IDX_OFF  8388609

// ============================ main GEMM config (R5 geometry, frozen) =======
#define MT          128                  // z rows per CTA
#define NMMACTA     (NROWS / MT)         // 256 CTAs
#define NCODE       128                  // codes per chunk
#define NCHUNKS     (KCODES / NCODE)     // 32
#define DELTA       3.0e-4f              // provable-argmin margin (fp16 approx)

#define ROW_BYTES   528                  // 256 fp16 + 16B pad (LDSM conflict-free)
#define TILE_BYTES  (128 * ROW_BYTES)    // 67584 per A / B buffer
#define SM_A        0
#define SM_B0       TILE_BYTES
#define SM_B1       (2 * TILE_BYTES)
#define SM_MRG      (3 * TILE_BYTES)     // 5 arrays x 512 x 4B = 10240
#define SM_TOTAL    (3 * TILE_BYTES + 10240)  // 212992 bytes (< 227KB cap)

// epilogue kernel tiling
#define EP_ROWS   64
#define EP_NCTA   (NROWS / EP_ROWS)      // 512
#define EP_THREADS 256
#define EP_STRIDE 260                    // floats; multiple of 4 -> aligned float4
#define EP_SMEM   (EP_ROWS * EP_STRIDE * 4)   // 66560 bytes dynamic

// ============================ device globals ===============================
__device__ float  g_esq[KCODES];
__device__ int    g_idx[NROWS];
__device__ double g_partials[EP_NCTA];
__device__ __align__(16) __half g_zh[NROWS * DIMS];        // z, row-major fp16
__device__ __align__(16) __half g_cbh[KCODES * DIMS];      // codebook fp16
__device__ int g_ucount;                 // rows needing full 4096-code rescan
__device__ int g_ulist[NROWS];
__device__ int g_pcount;                 // rows needing 2-candidate rescore
__device__ int g_pn[NROWS];
__device__ int g_pa[NROWS];
__device__ int g_pb[NROWS];

// ============================ PTX helpers ==================================
__device__ __forceinline__ uint32_t smem_u32(const void* p) {
    uint32_t a;
    asm("{ .reg .u64 t; cvta.to.shared.u64 t, %1; cvt.u32.u64 %0, t; }"
        : "=r"(a) : "l"(p));
    return a;
}

#define CP_ASYNC16(dst, src) \
    asm volatile("cp.async.cg.shared.global [%0], [%1], 16;" \
                 :: "r"(dst), "l"(src) : "memory")
#define CP_COMMIT() asm volatile("cp.async.commit_group;" ::: "memory")
#define CP_WAIT(n)  asm volatile("cp.async.wait_group %0;" :: "n"(n) : "memory")

#define LDSM_X4(r0, r1, r2, r3, addr) \
    asm volatile("ldmatrix.sync.aligned.m8n8.x4.shared.b16 {%0,%1,%2,%3}, [%4];" \
                 : "=r"(r0), "=r"(r1), "=r"(r2), "=r"(r3) : "r"(addr))

#define MMA_F16(acc, a, b0, b1) \
    asm volatile("mma.sync.aligned.m16n8k16.row.col.f32.f16.f16.f32 " \
        "{%0,%1,%2,%3}, {%4,%5,%6,%7}, {%8,%9}, {%0,%1,%2,%3};" \
        : "+f"((acc)[0]), "+f"((acc)[1]), "+f"((acc)[2]), "+f"((acc)[3]) \
        : "r"((a)[0]), "r"((a)[1]), "r"((a)[2]), "r"((a)[3]), \
          "r"(b0), "r"(b1))

__device__ __forceinline__ uint32_t pack_f16x2(float a0, float a1) {
    __half2 h2 = __floats2half2_rn(a0, a1);
    return *reinterpret_cast<uint32_t*>(&h2);
}

// insert (d, k) into running top-3 (v1,i1,v2,i2,v3)
__device__ __forceinline__ void ins3(float d, int k,
                                     float& v1, int& i1,
                                     float& v2, int& i2, float& v3) {
    if (d < v3) {
        if (d < v1)      { v3 = v2; v2 = v1; i2 = i1; v1 = d; i1 = k; }
        else if (d < v2) { v3 = v2; v2 = d;  i2 = k; }
        else             { v3 = d; }
    }
}

// ============================ kernel 0a: z transpose -> fp16 ===============
__global__ void vq_zprep(const float* __restrict__ z) {
    __shared__ float tile[32][33];
    const int bidx = blockIdx.x;              // 32 b * 8 dt * 32 ht = 8192
    const int b  = bidx >> 8;
    const int dt = (bidx >> 5) & 7;
    const int ht = bidx & 31;
    const int tx = threadIdx.x & 31;
    const int ty = threadIdx.x >> 5;          // 0..7
    const float* zp = z + ((size_t)b * 256 + dt * 32) * 1024 + ht * 32;
    #pragma unroll
    for (int i = 0; i < 4; ++i)
        tile[ty + 8 * i][tx] = zp[(size_t)(ty + 8 * i) * 1024 + tx];
    __syncthreads();
    __half* dst = g_zh + ((size_t)b * 1024 + ht * 32) * 256 + dt * 32;
    #pragma unroll
    for (int i = 0; i < 4; ++i) {
        int r = ty + 8 * i;
        dst[(size_t)r * 256 + tx] = __float2half(tile[tx][r]);
    }
}

// ============== kernel 0b: cb -> fp16 + e_sq + counter reset (merged) ======
__global__ void vq_cbprep(const float* __restrict__ cb) {
    const int warp = blockIdx.x * 8 + (threadIdx.x >> 5);
    const int lane = threadIdx.x & 31;
    if (blockIdx.x == 0 && threadIdx.x == 0) { g_ucount = 0; g_pcount = 0; }
    if (warp >= KCODES) return;
    const float4* row = reinterpret_cast<const float4*>(cb) + (size_t)warp * 64;
    float4 v0 = row[lane];
    float4 v1 = row[lane + 32];
    float s = 0.0f;
    s = fmaf(v0.x, v0.x, s); s = fmaf(v0.y, v0.y, s);
    s = fmaf(v0.z, v0.z, s); s = fmaf(v0.w, v0.w, s);
    s = fmaf(v1.x, v1.x, s); s = fmaf(v1.y, v1.y, s);
    s = fmaf(v1.z, v1.z, s); s = fmaf(v1.w, v1.w, s);
    uint2 p0, p1;
    p0.x = pack_f16x2(v0.x, v0.y); p0.y = pack_f16x2(v0.z, v0.w);
    p1.x = pack_f16x2(v1.x, v1.y); p1.y = pack_f16x2(v1.z, v1.w);
    uint2* dst = reinterpret_cast<uint2*>(g_cbh + (size_t)warp * DIMS);
    dst[lane]      = p0;
    dst[lane + 32] = p1;
    #pragma unroll
    for (int o = 16; o > 0; o >>= 1) s += __shfl_down_sync(0xffffffffu, s, o);
    if (lane == 0) g_esq[warp] = s;
}

// ============================ kernel 1: HMMA GEMM + top-3 margin argmin ====
__global__ void __launch_bounds__(256, 1)
vq_mma_kernel() {
    extern __shared__ char sm[];
    const uint32_t smb = smem_u32(sm);
    const int tid  = threadIdx.x;
    const int lane = tid & 31;
    const int w    = tid >> 5;
    const int mw   = w & 1;
    const int nw   = w >> 1;
    const int n0   = blockIdx.x * MT;

    // ---- stage A (z rows) + B chunk 0 via cp.async ----
    {
        const char* srcA = (const char*)g_zh + (size_t)n0 * 512;
        const char* srcB = (const char*)g_cbh;
        #pragma unroll
        for (int i = 0; i < 16; ++i) {
            int seg = tid + i * 256;
            int rc = seg >> 5, s = seg & 31;
            CP_ASYNC16(smb + SM_A + rc * ROW_BYTES + s * 16,
                       srcA + (size_t)rc * 512 + s * 16);
        }
        #pragma unroll
        for (int i = 0; i < 16; ++i) {
            int seg = tid + i * 256;
            int rc = seg >> 5, s = seg & 31;
            CP_ASYNC16(smb + SM_B0 + rc * ROW_BYTES + s * 16,
                       srcB + (size_t)rc * 512 + s * 16);
        }
        CP_COMMIT();
    }

    const uint32_t lr = (uint32_t)((lane & 7) + ((lane >> 3) & 1) * 8);
    const uint32_t ch = (uint32_t)((lane >> 4) & 1);
    const uint32_t a_base = smb + SM_A + (mw * 64 + lr) * ROW_BYTES + ch * 16;
    const uint32_t b_off  = (nw * 32 + lr) * ROW_BYTES + ch * 16;

    float v1[8], v2[8], v3[8]; int i1[8], i2[8];
    #pragma unroll
    for (int r = 0; r < 8; ++r) {
        v1[r] = FLT_MAX; v2[r] = FLT_MAX; v3[r] = FLT_MAX; i1[r] = 0; i2[r] = 0;
    }

    for (int c = 0; c < NCHUNKS; ++c) {
        if (c < NCHUNKS - 1) {
            const char* srcB = (const char*)g_cbh + (size_t)(c + 1) * NCODE * 512;
            uint32_t dstB = smb + (((c + 1) & 1) ? SM_B1 : SM_B0);
            #pragma unroll
            for (int i = 0; i < 16; ++i) {
                int seg = tid + i * 256;
                int rc = seg >> 5, s = seg & 31;
                CP_ASYNC16(dstB + rc * ROW_BYTES + s * 16,
                           srcB + (size_t)rc * 512 + s * 16);
            }
            CP_COMMIT();
            CP_WAIT(1);
        } else {
            CP_WAIT(0);
        }
        __syncthreads();

        const uint32_t bbuf = smb + ((c & 1) ? SM_B1 : SM_B0);

        float acc[4][4][4];
        #pragma unroll
        for (int mf = 0; mf < 4; ++mf)
            #pragma unroll
            for (int nf = 0; nf < 4; ++nf)
                #pragma unroll
                for (int i = 0; i < 4; ++i) acc[mf][nf][i] = 0.0f;

        #pragma unroll 4
        for (int ks = 0; ks < 16; ++ks) {
            uint32_t a[4][4];
            #pragma unroll
            for (int mf = 0; mf < 4; ++mf)
                LDSM_X4(a[mf][0], a[mf][1], a[mf][2], a[mf][3],
                        a_base + mf * (16 * ROW_BYTES) + ks * 32);
            uint32_t bf[2][4];
            #pragma unroll
            for (int p = 0; p < 2; ++p)
                LDSM_X4(bf[p][0], bf[p][1], bf[p][2], bf[p][3],
                        bbuf + b_off + p * (16 * ROW_BYTES) + ks * 32);
            #pragma unroll
            for (int mf = 0; mf < 4; ++mf) {
                #pragma unroll
                for (int p = 0; p < 2; ++p) {
                    MMA_F16(acc[mf][p * 2 + 0], a[mf], bf[p][0], bf[p][2]);
                    MMA_F16(acc[mf][p * 2 + 1], a[mf], bf[p][1], bf[p][3]);
                }
            }
        }

        // ---- shifted dists + running top-3 ----
        const int kbase = c * NCODE + nw * 32;
        #pragma unroll
        for (int nf = 0; nf < 4; ++nf) {
            int kc = kbase + nf * 8 + (lane & 3) * 2;
            float2 e2 = *reinterpret_cast<const float2*>(&g_esq[kc]);
            #pragma unroll
            for (int mf = 0; mf < 4; ++mf) {
                #pragma unroll
                for (int i = 0; i < 4; ++i) {
                    int ri = mf * 2 + (i >> 1);
                    float e = (i & 1) ? e2.y : e2.x;
                    float d = fmaf(-2.0f, acc[mf][nf][i], e);
                    ins3(d, kc + (i & 1), v1[ri], i1[ri], v2[ri], i2[ri], v3[ri]);
                }
            }
        }
        __syncthreads();
    }

    // ---- merge across the 4 lanes of each quad ----
    #pragma unroll
    for (int r = 0; r < 8; ++r) {
        #pragma unroll
        for (int off = 1; off < 4; off <<= 1) {
            float ov1 = __shfl_xor_sync(0xffffffffu, v1[r], off);
            float ov2 = __shfl_xor_sync(0xffffffffu, v2[r], off);
            float ov3 = __shfl_xor_sync(0xffffffffu, v3[r], off);
            int   oi1 = __shfl_xor_sync(0xffffffffu, i1[r], off);
            int   oi2 = __shfl_xor_sync(0xffffffffu, i2[r], off);
            ins3(ov1, oi1, v1[r], i1[r], v2[r], i2[r], v3[r]);
            ins3(ov2, oi2, v1[r], i1[r], v2[r], i2[r], v3[r]);
            ins3(ov3, -1,  v1[r], i1[r], v2[r], i2[r], v3[r]);
        }
    }

    // ---- cross-warp merge via smem, classification ----
    float* mv1 = reinterpret_cast<float*>(sm + SM_MRG);
    float* mv2 = mv1 + 512;
    float* mv3 = mv2 + 512;
    int*   mi1 = reinterpret_cast<int*>(mv3 + 512);
    int*   mi2 = mi1 + 512;
    if ((lane & 3) == 0) {
        int q = lane >> 2;
        #pragma unroll
        for (int mf = 0; mf < 4; ++mf)
            #pragma unroll
            for (int dlt = 0; dlt < 2; ++dlt) {
                int row = mw * 64 + mf * 16 + dlt * 8 + q;
                int r = mf * 2 + dlt;
                mv1[nw * 128 + row] = v1[r];
                mv2[nw * 128 + row] = v2[r];
                mv3[nw * 128 + row] = v3[r];
                mi1[nw * 128 + row] = i1[r];
                mi2[nw * 128 + row] = i2[r];
            }
    }
    __syncthreads();
    if (tid < 128) {
        float bv1 = mv1[tid], bv2 = mv2[tid], bv3 = mv3[tid];
        int   bi1 = mi1[tid], bi2 = mi2[tid];
        #pragma unroll
        for (int g = 1; g < 4; ++g) {
            ins3(mv1[g * 128 + tid], mi1[g * 128 + tid], bv1, bi1, bv2, bi2, bv3);
            ins3(mv2[g * 128 + tid], mi2[g * 128 + tid], bv1, bi1, bv2, bi2, bv3);
            ins3(mv3[g * 128 + tid], -1,                 bv1, bi1, bv2, bi2, bv3);
        }
        int n = n0 + tid;
        if (__fsub_rn(bv2, bv1) > DELTA) {
            g_idx[n] = bi1;                       // provably the reference argmin
        } else if (__fsub_rn(bv3, bv1) > DELTA) {
            int p = atomicAdd(&g_pcount, 1);      // exactly 2 candidates
            g_pn[p] = n; g_pa[p] = bi1; g_pb[p] = bi2;
        } else {
            int p = atomicAdd(&g_ucount, 1);      // rare 3-way near-tie
            g_ulist[p] = n;
        }
    }
}

// ============================ kernel 2a: 2-candidate exact rescore =========
// Warp per row; arithmetic identical to the validated full fallback:
// same zsq tree, sequential-d fmaf dot, fl(fl(zsq-2dot)+esq), min-index ties.
__global__ void __launch_bounds__(256)
vq_pair_kernel(const float* __restrict__ z, const float* __restrict__ cb) {
    __shared__ float zs[8][256];
    const int warp = threadIdx.x >> 5;
    const int lane = threadIdx.x & 31;
    const int cnt  = g_pcount;

    for (int idx = blockIdx.x * 8 + warp; idx < cnt; idx += gridDim.x * 8) {
        int n  = g_pn[idx];
        int ka = g_pa[idx];
        int kb = g_pb[idx];
        int bb = n >> 10, hw = n & 1023;

        // load z row: lane owns d = lane + 32j (matches fallback layout)
        float zv[8];
        #pragma unroll
        for (int j = 0; j < 8; ++j)
            zv[j] = z[((size_t)bb * 256 + lane + 32 * j) * 1024 + hw];

        // zsq: same per-lane chain + shuffle tree as the validated fallback
        float s = 0.0f;
        #pragma unroll
        for (int j = 0; j < 8; ++j) s = fmaf(zv[j], zv[j], s);
        #pragma unroll
        for (int o = 16; o > 0; o >>= 1) s += __shfl_down_sync(0xffffffffu, s, o);
        float zsq = __shfl_sync(0xffffffffu, s, 0);

        // stage z row to smem (conflict-free: consecutive lanes -> consecutive d)
        #pragma unroll
        for (int j = 0; j < 8; ++j) zs[warp][lane + 32 * j] = zv[j];
        __syncwarp();

        // lanes 0,1: sequential-d exact dot for their candidate
        float dist = 0.0f;
        if (lane < 2) {
            int myk = (lane == 0) ? ka : kb;
            const float* er = cb + (size_t)myk * DIMS;
            float dot = 0.0f;
            #pragma unroll 8
            for (int d = 0; d < 256; ++d)
                dot = fmaf(zs[warp][d], er[d], dot);
            dist = __fadd_rn(__fsub_rn(zsq, __fmul_rn(2.0f, dot)), g_esq[myk]);
        }
        float da = __shfl_sync(0xffffffffu, dist, 0);
        float db = __shfl_sync(0xffffffffu, dist, 1);
        if (lane == 0) {
            int win;
            if (db < da)      win = kb;
            else if (da < db) win = ka;
            else              win = min(ka, kb);   // first-index tie-break
            g_idx[n] = win;
        }
        __syncwarp();
    }
}

// ============================ kernel 2b: full exact fallback (validated) ===
__global__ void __launch_bounds__(512)
vq_fallback_kernel(const float* __restrict__ z, const float* __restrict__ cb) {
    __shared__ float zrow[8][256];
    __shared__ float zsqs[8];
    __shared__ int   rown[8];
    __shared__ unsigned long long red[512];

    const int t = threadIdx.x;
    const int cnt = g_ucount;

    for (int base = blockIdx.x * 8; base < cnt; base += gridDim.x * 8) {
        const int nr = min(8, cnt - base);
        if (t < nr) rown[t] = g_ulist[base + t];
        __syncthreads();
        for (int e = t; e < nr * 256; e += 512) {
            int j = e >> 8, d = e & 255;
            int n = rown[j], bb = n >> 10, hw = n & 1023;
            zrow[j][d] = z[((size_t)bb * 256 + d) * 1024 + hw];
        }
        __syncthreads();
        {
            int wj = t >> 5, lane = t & 31;
            if (wj < nr) {
                float s = 0.0f;
                #pragma unroll
                for (int j = 0; j < 8; ++j) {
                    float v = zrow[wj][lane + 32 * j];
                    s = fmaf(v, v, s);
                }
                #pragma unroll
                for (int o = 16; o > 0; o >>= 1) s += __shfl_down_sync(0xffffffffu, s, o);
                if (lane == 0) zsqs[wj] = s;
            }
        }
        __syncthreads();

        unsigned long long best[8];
        #pragma unroll
        for (int j = 0; j < 8; ++j) best[j] = ~0ull;

        for (int k = t; k < KCODES; k += 512) {
            const float4* er = reinterpret_cast<const float4*>(cb + (size_t)k * DIMS);
            float dot[8];
            #pragma unroll
            for (int j = 0; j < 8; ++j) dot[j] = 0.0f;
            for (int q = 0; q < 64; ++q) {
                float4 e4 = er[q];
                float ev[4] = {e4.x, e4.y, e4.z, e4.w};
                #pragma unroll
                for (int x = 0; x < 4; ++x) {
                    int d = q * 4 + x;
                    #pragma unroll
                    for (int j = 0; j < 8; ++j)
                        dot[j] = fmaf(zrow[j][d], ev[x], dot[j]);
                }
            }
            float es = g_esq[k];
            #pragma unroll
            for (int j = 0; j < 8; ++j) {
                float dist = __fadd_rn(__fsub_rn(zsqs[j], __fmul_rn(2.0f, dot[j])), es);
                unsigned long long p =
                    ((unsigned long long)__float_as_uint(dist) << 32) | (unsigned)k;
                if (p < best[j]) best[j] = p;
            }
        }

        for (int j = 0; j < nr; ++j) {
            red[t] = best[j];
            __syncthreads();
            for (int s2 = 256; s2 > 0; s2 >>= 1) {
                if (t < s2) { if (red[t + s2] < red[t]) red[t] = red[t + s2]; }
                __syncthreads();
            }
            if (t == 0) g_idx[rown[j]] = (int)(red[0] & 0xffffffffu);
            __syncthreads();
        }
        __syncthreads();
    }
}

// ============================ kernel 3: output epilogue (two-phase, R9) ====
__global__ void __launch_bounds__(EP_THREADS)
vq_epilogue_kernel(const float* __restrict__ z, const float* __restrict__ cb,
                   float* __restrict__ out, int out_size) {
    extern __shared__ float zq[];                 // [64][EP_STRIDE]
    __shared__ int idx_s[EP_ROWS];
    __shared__ double red[EP_THREADS];

    const int t  = threadIdx.x;
    const int n0 = blockIdx.x * EP_ROWS;

    if (t < EP_ROWS) {
        int ii = g_idx[n0 + t];
        idx_s[t] = ii;
        int oi = IDX_OFF + n0 + t;
        if (oi < out_size) out[oi] = (float)ii;
    }
    __syncthreads();

    {
        const int wj   = t >> 5;
        const int lane = t & 31;
        #pragma unroll
        for (int rr = 0; rr < 8; ++rr) {
            int row = wj * 8 + rr;
            const float4* src = reinterpret_cast<const float4*>(
                cb + (size_t)idx_s[row] * DIMS);
            float4 q0 = src[lane];
            float4 q1 = src[lane + 32];
            float* dst = &zq[row * EP_STRIDE];
            *reinterpret_cast<float4*>(dst + lane * 4)       = q0;
            *reinterpret_cast<float4*>(dst + 128 + lane * 4) = q1;
        }
    }
    __syncthreads();

    const int b   = n0 >> 10;
    const int hw0 = n0 & 1023;
    const float* zb = z + ((size_t)b * 256) * 1024 + hw0;
    float*       ob = out + ((size_t)b * 256) * 1024 + hw0;

    const int r  = t & 63;
    const int dq = t >> 6;
    const float* qrow = &zq[r * EP_STRIDE];

    double accd = 0.0;
    #pragma unroll 8
    for (int p = 0; p < 64; ++p) {
        int d = dq * 64 + p;
        float qv = qrow[d];
        float zv = zb[(size_t)d * 1024 + r];
        float diff = __fsub_rn(qv, zv);
        ob[(size_t)d * 1024 + r] = __fadd_rn(zv, diff);   // straight-through
        accd = fma((double)diff, (double)diff, accd);
    }

    red[t] = accd;
    __syncthreads();
    for (int s = EP_THREADS / 2; s > 0; s >>= 1) {
        if (t < s) red[t] += red[t + s];
        __syncthreads();
    }
    if (t == 0) g_partials[blockIdx.x] = red[0];
}

// ============================ kernel 4: finalize loss ======================
__global__ void vq_finalize_kernel(float* __restrict__ out, int out_size) {
    __shared__ double red[256];
    const int t = threadIdx.x;
    red[t] = g_partials[t] + g_partials[t + 256];
    __syncthreads();
    for (int s = 128; s > 0; s >>= 1) {
        if (t < s) red[t] += red[t + s];
        __syncthreads();
    }
    if (t == 0 && LOSS_OFF < out_size) {
        double mean = red[0] / (double)ZELEMS;
        float m = (float)mean;
        out[LOSS_OFF] = __fadd_rn(m, __fmul_rn(0.25f, m));
    }
}

// ============================ launch ======================================
extern "C" void kernel_launch(void* const* d_in, const int* in_sizes, int n_in,
                              void* d_out, int out_size) {
    const float* z  = (const float*)d_in[0];
    const float* cb = (const float*)d_in[1];
    if (n_in >= 2 && in_sizes[0] == KCODES * DIMS && in_sizes[1] == ZELEMS) {
        const float* tmp = z; z = cb; cb = tmp;
    }
    float* out = (float*)d_out;

    cudaFuncSetAttribute(vq_mma_kernel,
                         cudaFuncAttributeMaxDynamicSharedMemorySize, SM_TOTAL);
    cudaFuncSetAttribute(vq_epilogue_kernel,
                         cudaFuncAttributeMaxDynamicSharedMemorySize, EP_SMEM);

    vq_zprep<<<8192, 256>>>(z);
    vq_cbprep<<<KCODES / 8, 256>>>(cb);
    vq_mma_kernel<<<NMMACTA, 256, SM_TOTAL>>>();
    vq_pair_kernel<<<148, 256>>>(z, cb);
    vq_fallback_kernel<<<128, 512>>>(z, cb);
    vq_epilogue_kernel<<<EP_NCTA, EP_THREADS, EP_SMEM>>>(z, cb, out, out_size);
    vq_finalize_kernel<<<1, 256>>>(out, out_size);
}

// round 11
// speedup vs baseline: 1.3233x; 1.3233x over previous
#include <cuda_runtime.h>
#include <cuda_fp16.h>
#include <float.h>
#include <stdint.h>

// ============================ problem constants ============================
#define KCODES   4096
#define DIMS     256
#define NROWS    32768
#define ZELEMS   8388608
#define LOSS_OFF 8388608
#define IDX_OFF  8388609

// ============================ main GEMM config (R5/R9 geometry, frozen) ====
#define MT          128                  // z rows per CTA
#define NMMACTA     (NROWS / MT)         // 256 CTAs
#define NCODE       128                  // codes per chunk
#define NCHUNKS     (KCODES / NCODE)     // 32
#define DELTA       3.0e-4f              // provable-argmin margin (fp16 approx)

#define ROW_BYTES   528                  // 256 fp16 + 16B pad (LDSM conflict-free)
#define TILE_BYTES  (128 * ROW_BYTES)    // 67584 per A / B buffer
#define SM_A        0
#define SM_B0       TILE_BYTES
#define SM_B1       (2 * TILE_BYTES)
#define SM_MRG      (3 * TILE_BYTES)     // 2*512 floats + 512 ints = 6144
#define SM_TOTAL    (3 * TILE_BYTES + 6144)   // 208896 bytes

// fallback task decomposition
#define FB_ROWS   8                      // rows per batch
#define FB_CODES  512                    // codes per task chunk
#define FB_CHUNKS (KCODES / FB_CODES)    // 8

// epilogue kernel tiling (validated R9)
#define EP_ROWS   64
#define EP_NCTA   (NROWS / EP_ROWS)      // 512
#define EP_THREADS 256
#define EP_STRIDE 260                    // floats; multiple of 4 -> aligned float4
#define EP_SMEM   (EP_ROWS * EP_STRIDE * 4)   // 66560 bytes dynamic

// ============================ device globals ===============================
__device__ float  g_esq[KCODES];
__device__ int    g_idx[NROWS];
__device__ double g_partials[EP_NCTA];
__device__ __align__(16) __half g_zh[NROWS * DIMS];        // z, row-major fp16
__device__ __align__(16) __half g_cbh[KCODES * DIMS];      // codebook fp16
__device__ int g_ucount;
__device__ int g_ulist[NROWS];
__device__ unsigned long long g_best[NROWS];               // packed (dist,k)

// ============================ PTX helpers ==================================
__device__ __forceinline__ uint32_t smem_u32(const void* p) {
    uint32_t a;
    asm("{ .reg .u64 t; cvta.to.shared.u64 t, %1; cvt.u32.u64 %0, t; }"
        : "=r"(a) : "l"(p));
    return a;
}

#define CP_ASYNC16(dst, src) \
    asm volatile("cp.async.cg.shared.global [%0], [%1], 16;" \
                 :: "r"(dst), "l"(src) : "memory")
#define CP_COMMIT() asm volatile("cp.async.commit_group;" ::: "memory")
#define CP_WAIT(n)  asm volatile("cp.async.wait_group %0;" :: "n"(n) : "memory")

#define LDSM_X4(r0, r1, r2, r3, addr) \
    asm volatile("ldmatrix.sync.aligned.m8n8.x4.shared.b16 {%0,%1,%2,%3}, [%4];" \
                 : "=r"(r0), "=r"(r1), "=r"(r2), "=r"(r3) : "r"(addr))

#define MMA_F16(acc, a, b0, b1) \
    asm volatile("mma.sync.aligned.m16n8k16.row.col.f32.f16.f16.f32 " \
        "{%0,%1,%2,%3}, {%4,%5,%6,%7}, {%8,%9}, {%0,%1,%2,%3};" \
        : "+f"((acc)[0]), "+f"((acc)[1]), "+f"((acc)[2]), "+f"((acc)[3]) \
        : "r"((a)[0]), "r"((a)[1]), "r"((a)[2]), "r"((a)[3]), \
          "r"(b0), "r"(b1))

__device__ __forceinline__ uint32_t pack_f16x2(float a0, float a1) {
    __half2 h2 = __floats2half2_rn(a0, a1);
    return *reinterpret_cast<uint32_t*>(&h2);
}

// ============================ kernel 0a: z transpose -> fp16 ===============
__global__ void vq_zprep(const float* __restrict__ z) {
    __shared__ float tile[32][33];
    const int bidx = blockIdx.x;              // 32 b * 8 dt * 32 ht = 8192
    const int b  = bidx >> 8;
    const int dt = (bidx >> 5) & 7;
    const int ht = bidx & 31;
    const int tx = threadIdx.x & 31;
    const int ty = threadIdx.x >> 5;          // 0..7
    const float* zp = z + ((size_t)b * 256 + dt * 32) * 1024 + ht * 32;
    #pragma unroll
    for (int i = 0; i < 4; ++i)
        tile[ty + 8 * i][tx] = zp[(size_t)(ty + 8 * i) * 1024 + tx];
    __syncthreads();
    __half* dst = g_zh + ((size_t)b * 1024 + ht * 32) * 256 + dt * 32;
    #pragma unroll
    for (int i = 0; i < 4; ++i) {
        int r = ty + 8 * i;
        dst[(size_t)r * 256 + tx] = __float2half(tile[tx][r]);
    }
}

// ============== kernel 0b: cb -> fp16 + e_sq + counter reset (merged) ======
__global__ void vq_cbprep(const float* __restrict__ cb) {
    const int warp = blockIdx.x * 8 + (threadIdx.x >> 5);
    const int lane = threadIdx.x & 31;
    if (blockIdx.x == 0 && threadIdx.x == 0) g_ucount = 0;
    if (warp >= KCODES) return;
    const float4* row = reinterpret_cast<const float4*>(cb) + (size_t)warp * 64;
    float4 v0 = row[lane];
    float4 v1 = row[lane + 32];
    float s = 0.0f;
    s = fmaf(v0.x, v0.x, s); s = fmaf(v0.y, v0.y, s);
    s = fmaf(v0.z, v0.z, s); s = fmaf(v0.w, v0.w, s);
    s = fmaf(v1.x, v1.x, s); s = fmaf(v1.y, v1.y, s);
    s = fmaf(v1.z, v1.z, s); s = fmaf(v1.w, v1.w, s);
    uint2 p0, p1;
    p0.x = pack_f16x2(v0.x, v0.y); p0.y = pack_f16x2(v0.z, v0.w);
    p1.x = pack_f16x2(v1.x, v1.y); p1.y = pack_f16x2(v1.z, v1.w);
    uint2* dst = reinterpret_cast<uint2*>(g_cbh + (size_t)warp * DIMS);
    dst[lane]      = p0;
    dst[lane + 32] = p1;
    #pragma unroll
    for (int o = 16; o > 0; o >>= 1) s += __shfl_down_sync(0xffffffffu, s, o);
    if (lane == 0) g_esq[warp] = s;
}

// ============================ kernel 1: HMMA GEMM + margin argmin (R9) =====
__global__ void __launch_bounds__(256, 1)
vq_mma_kernel() {
    extern __shared__ char sm[];
    const uint32_t smb = smem_u32(sm);
    const int tid  = threadIdx.x;
    const int lane = tid & 31;
    const int w    = tid >> 5;
    const int mw   = w & 1;
    const int nw   = w >> 1;
    const int n0   = blockIdx.x * MT;

    // ---- stage A (z rows) + B chunk 0 via cp.async ----
    {
        const char* srcA = (const char*)g_zh + (size_t)n0 * 512;
        const char* srcB = (const char*)g_cbh;
        #pragma unroll
        for (int i = 0; i < 16; ++i) {
            int seg = tid + i * 256;
            int rc = seg >> 5, s = seg & 31;
            CP_ASYNC16(smb + SM_A + rc * ROW_BYTES + s * 16,
                       srcA + (size_t)rc * 512 + s * 16);
        }
        #pragma unroll
        for (int i = 0; i < 16; ++i) {
            int seg = tid + i * 256;
            int rc = seg >> 5, s = seg & 31;
            CP_ASYNC16(smb + SM_B0 + rc * ROW_BYTES + s * 16,
                       srcB + (size_t)rc * 512 + s * 16);
        }
        CP_COMMIT();
    }

    const uint32_t lr = (uint32_t)((lane & 7) + ((lane >> 3) & 1) * 8);
    const uint32_t ch = (uint32_t)((lane >> 4) & 1);
    const uint32_t a_base = smb + SM_A + (mw * 64 + lr) * ROW_BYTES + ch * 16;
    const uint32_t b_off  = (nw * 32 + lr) * ROW_BYTES + ch * 16;

    float v1[8], v2[8]; int i1[8];
    #pragma unroll
    for (int r = 0; r < 8; ++r) { v1[r] = FLT_MAX; v2[r] = FLT_MAX; i1[r] = 0; }

    for (int c = 0; c < NCHUNKS; ++c) {
        if (c < NCHUNKS - 1) {
            const char* srcB = (const char*)g_cbh + (size_t)(c + 1) * NCODE * 512;
            uint32_t dstB = smb + (((c + 1) & 1) ? SM_B1 : SM_B0);
            #pragma unroll
            for (int i = 0; i < 16; ++i) {
                int seg = tid + i * 256;
                int rc = seg >> 5, s = seg & 31;
                CP_ASYNC16(dstB + rc * ROW_BYTES + s * 16,
                           srcB + (size_t)rc * 512 + s * 16);
            }
            CP_COMMIT();
            CP_WAIT(1);
        } else {
            CP_WAIT(0);
        }
        __syncthreads();

        const uint32_t bbuf = smb + ((c & 1) ? SM_B1 : SM_B0);

        float acc[4][4][4];
        #pragma unroll
        for (int mf = 0; mf < 4; ++mf)
            #pragma unroll
            for (int nf = 0; nf < 4; ++nf)
                #pragma unroll
                for (int i = 0; i < 4; ++i) acc[mf][nf][i] = 0.0f;

        #pragma unroll 4
        for (int ks = 0; ks < 16; ++ks) {
            uint32_t a[4][4];
            #pragma unroll
            for (int mf = 0; mf < 4; ++mf)
                LDSM_X4(a[mf][0], a[mf][1], a[mf][2], a[mf][3],
                        a_base + mf * (16 * ROW_BYTES) + ks * 32);
            uint32_t bf[2][4];
            #pragma unroll
            for (int p = 0; p < 2; ++p)
                LDSM_X4(bf[p][0], bf[p][1], bf[p][2], bf[p][3],
                        bbuf + b_off + p * (16 * ROW_BYTES) + ks * 32);
            #pragma unroll
            for (int mf = 0; mf < 4; ++mf) {
                #pragma unroll
                for (int p = 0; p < 2; ++p) {
                    MMA_F16(acc[mf][p * 2 + 0], a[mf], bf[p][0], bf[p][2]);
                    MMA_F16(acc[mf][p * 2 + 1], a[mf], bf[p][1], bf[p][3]);
                }
            }
        }

        // ---- shifted dists + running (best, second-best) ----
        const int kbase = c * NCODE + nw * 32;
        #pragma unroll
        for (int nf = 0; nf < 4; ++nf) {
            int kc = kbase + nf * 8 + (lane & 3) * 2;
            float2 e2 = *reinterpret_cast<const float2*>(&g_esq[kc]);
            #pragma unroll
            for (int mf = 0; mf < 4; ++mf) {
                #pragma unroll
                for (int i = 0; i < 4; ++i) {
                    int ri = mf * 2 + (i >> 1);
                    float e = (i & 1) ? e2.y : e2.x;
                    float d = fmaf(-2.0f, acc[mf][nf][i], e);
                    if (d < v2[ri]) {
                        if (d < v1[ri]) {
                            v2[ri] = v1[ri]; v1[ri] = d; i1[ri] = kc + (i & 1);
                        } else v2[ri] = d;
                    }
                }
            }
        }
        __syncthreads();
    }

    // ---- merge across the 4 lanes of each quad ----
    #pragma unroll
    for (int r = 0; r < 8; ++r) {
        #pragma unroll
        for (int off = 1; off < 4; off <<= 1) {
            float ov1 = __shfl_xor_sync(0xffffffffu, v1[r], off);
            float ov2 = __shfl_xor_sync(0xffffffffu, v2[r], off);
            int   oi  = __shfl_xor_sync(0xffffffffu, i1[r], off);
            float lo = fminf(v1[r], ov1);
            float hi = fmaxf(v1[r], ov1);
            float s2 = fminf(fminf(v2[r], ov2), hi);
            if (ov1 < v1[r] || (ov1 == v1[r] && oi < i1[r])) i1[r] = oi;
            v1[r] = lo; v2[r] = s2;
        }
    }

    // ---- cross-warp merge via smem, margin test ----
    float* mv1 = reinterpret_cast<float*>(sm + SM_MRG);
    float* mv2 = mv1 + 512;
    int*   mi  = reinterpret_cast<int*>(mv2 + 512);
    if ((lane & 3) == 0) {
        int q = lane >> 2;
        #pragma unroll
        for (int mf = 0; mf < 4; ++mf)
            #pragma unroll
            for (int dlt = 0; dlt < 2; ++dlt) {
                int row = mw * 64 + mf * 16 + dlt * 8 + q;
                int r = mf * 2 + dlt;
                mv1[nw * 128 + row] = v1[r];
                mv2[nw * 128 + row] = v2[r];
                mi [nw * 128 + row] = i1[r];
            }
    }
    __syncthreads();
    if (tid < 128) {
        float bv1 = mv1[tid], bv2 = mv2[tid];
        int   bi  = mi[tid];
        #pragma unroll
        for (int g = 1; g < 4; ++g) {
            float ov1 = mv1[g * 128 + tid], ov2 = mv2[g * 128 + tid];
            int   oi  = mi[g * 128 + tid];
            float lo = fminf(bv1, ov1);
            float hi = fmaxf(bv1, ov1);
            bv2 = fminf(fminf(bv2, ov2), hi);
            if (ov1 < bv1 || (ov1 == bv1 && oi < bi)) bi = oi;
            bv1 = lo;
        }
        int n = n0 + tid;
        if (__fsub_rn(bv2, bv1) > DELTA) {
            g_idx[n] = bi;                      // provably the reference argmin
        } else {
            g_best[n] = ~0ull;                  // init packed-min slot
            int p = atomicAdd(&g_ucount, 1);    // near-tie -> exact rescore
            g_ulist[p] = n;
        }
    }
}

// ============================ kernel 2: exact fallback (task-parallel) =====
// Task = (8-row batch) x (512-code chunk). Per-(row,code) arithmetic is
// identical to the validated fallback: same zrow layout, same zsq shuffle
// tree, d-ordered fmaf dot, fl(fl(zsq-2dot)+esq). Merge via atomicMin on
// packed (dist_bits<<32)|k — dist>0 so float bits are order-monotonic;
// ties resolve to min k = first index. Order-independent -> deterministic.
__global__ void __launch_bounds__(512)
vq_fallback_kernel(const float* __restrict__ z, const float* __restrict__ cb) {
    __shared__ float zrow[FB_ROWS][256];
    __shared__ float zsqs[FB_ROWS];
    __shared__ int   rown[FB_ROWS];

    const int t = threadIdx.x;
    const int cnt = g_ucount;
    const int nbatch = (cnt + FB_ROWS - 1) / FB_ROWS;
    const int ntasks = nbatch * FB_CHUNKS;

    for (int task = blockIdx.x; task < ntasks; task += gridDim.x) {
        const int batch = task >> 3;            // FB_CHUNKS = 8
        const int chunk = task & 7;
        const int base  = batch * FB_ROWS;
        const int nr    = min(FB_ROWS, cnt - base);

        if (t < nr) rown[t] = g_ulist[base + t];
        __syncthreads();
        for (int e = t; e < nr * 256; e += 512) {
            int j = e >> 8, d = e & 255;
            int n = rown[j], bb = n >> 10, hw = n & 1023;
            zrow[j][d] = z[((size_t)bb * 256 + d) * 1024 + hw];
        }
        __syncthreads();
        {
            int wj = t >> 5, lane = t & 31;
            if (wj < nr) {
                float s = 0.0f;
                #pragma unroll
                for (int j = 0; j < 8; ++j) {
                    float v = zrow[wj][lane + 32 * j];
                    s = fmaf(v, v, s);
                }
                #pragma unroll
                for (int o = 16; o > 0; o >>= 1) s += __shfl_down_sync(0xffffffffu, s, o);
                if (lane == 0) zsqs[wj] = s;
            }
        }
        __syncthreads();

        // one code per thread within this chunk
        const int k = chunk * FB_CODES + t;
        const float4* er = reinterpret_cast<const float4*>(cb + (size_t)k * DIMS);
        float dot[FB_ROWS];
        #pragma unroll
        for (int j = 0; j < FB_ROWS; ++j) dot[j] = 0.0f;
        for (int q = 0; q < 64; ++q) {
            float4 e4 = er[q];
            float ev[4] = {e4.x, e4.y, e4.z, e4.w};
            #pragma unroll
            for (int x = 0; x < 4; ++x) {
                int d = q * 4 + x;
                #pragma unroll
                for (int j = 0; j < FB_ROWS; ++j)
                    dot[j] = fmaf(zrow[j][d], ev[x], dot[j]);
            }
        }
        float es = g_esq[k];
        for (int j = 0; j < nr; ++j) {
            float dist = __fadd_rn(__fsub_rn(zsqs[j], __fmul_rn(2.0f, dot[j])), es);
            unsigned long long p =
                ((unsigned long long)__float_as_uint(dist) << 32) | (unsigned)k;
            atomicMin(&g_best[rown[j]], p);
        }
        __syncthreads();   // smem reuse across tasks
    }
}

// ============================ kernel 2b: resolve packed minima =============
__global__ void vq_resolve_kernel() {
    const int cnt = g_ucount;
    for (int i = blockIdx.x * blockDim.x + threadIdx.x; i < cnt;
         i += gridDim.x * blockDim.x) {
        int n = g_ulist[i];
        g_idx[n] = (int)(g_best[n] & 0xffffffffu);
    }
}

// ============================ kernel 3: output epilogue (two-phase, R9) ====
__global__ void __launch_bounds__(EP_THREADS)
vq_epilogue_kernel(const float* __restrict__ z, const float* __restrict__ cb,
                   float* __restrict__ out, int out_size) {
    extern __shared__ float zq[];                 // [64][EP_STRIDE]
    __shared__ int idx_s[EP_ROWS];
    __shared__ double red[EP_THREADS];

    const int t  = threadIdx.x;
    const int n0 = blockIdx.x * EP_ROWS;

    if (t < EP_ROWS) {
        int ii = g_idx[n0 + t];
        idx_s[t] = ii;
        int oi = IDX_OFF + n0 + t;
        if (oi < out_size) out[oi] = (float)ii;
    }
    __syncthreads();

    {
        const int wj   = t >> 5;
        const int lane = t & 31;
        #pragma unroll
        for (int rr = 0; rr < 8; ++rr) {
            int row = wj * 8 + rr;
            const float4* src = reinterpret_cast<const float4*>(
                cb + (size_t)idx_s[row] * DIMS);
            float4 q0 = src[lane];
            float4 q1 = src[lane + 32];
            float* dst = &zq[row * EP_STRIDE];
            *reinterpret_cast<float4*>(dst + lane * 4)       = q0;
            *reinterpret_cast<float4*>(dst + 128 + lane * 4) = q1;
        }
    }
    __syncthreads();

    const int b   = n0 >> 10;
    const int hw0 = n0 & 1023;
    const float* zb = z + ((size_t)b * 256) * 1024 + hw0;
    float*       ob = out + ((size_t)b * 256) * 1024 + hw0;

    const int r  = t & 63;
    const int dq = t >> 6;
    const float* qrow = &zq[r * EP_STRIDE];

    double accd = 0.0;
    #pragma unroll 8
    for (int p = 0; p < 64; ++p) {
        int d = dq * 64 + p;
        float qv = qrow[d];
        float zv = zb[(size_t)d * 1024 + r];
        float diff = __fsub_rn(qv, zv);
        ob[(size_t)d * 1024 + r] = __fadd_rn(zv, diff);   // straight-through
        accd = fma((double)diff, (double)diff, accd);
    }

    red[t] = accd;
    __syncthreads();
    for (int s = EP_THREADS / 2; s > 0; s >>= 1) {
        if (t < s) red[t] += red[t + s];
        __syncthreads();
    }
    if (t == 0) g_partials[blockIdx.x] = red[0];
}

// ============================ kernel 4: finalize loss ======================
__global__ void vq_finalize_kernel(float* __restrict__ out, int out_size) {
    __shared__ double red[256];
    const int t = threadIdx.x;
    red[t] = g_partials[t] + g_partials[t + 256];
    __syncthreads();
    for (int s = 128; s > 0; s >>= 1) {
        if (t < s) red[t] += red[t + s];
        __syncthreads();
    }
    if (t == 0 && LOSS_OFF < out_size) {
        double mean = red[0] / (double)ZELEMS;
        float m = (float)mean;
        out[LOSS_OFF] = __fadd_rn(m, __fmul_rn(0.25f, m));
    }
}

// ============================ launch ======================================
extern "C" void kernel_launch(void* const* d_in, const int* in_sizes, int n_in,
                              void* d_out, int out_size) {
    const float* z  = (const float*)d_in[0];
    const float* cb = (const float*)d_in[1];
    if (n_in >= 2 && in_sizes[0] == KCODES * DIMS && in_sizes[1] == ZELEMS) {
        const float* tmp = z; z = cb; cb = tmp;
    }
    float* out = (float*)d_out;

    cudaFuncSetAttribute(vq_mma_kernel,
                         cudaFuncAttributeMaxDynamicSharedMemorySize, SM_TOTAL);
    cudaFuncSetAttribute(vq_epilogue_kernel,
                         cudaFuncAttributeMaxDynamicSharedMemorySize, EP_SMEM);

    vq_zprep<<<8192, 256>>>(z);
    vq_cbprep<<<KCODES / 8, 256>>>(cb);
    vq_mma_kernel<<<NMMACTA, 256, SM_TOTAL>>>();
    vq_fallback_kernel<<<512, 512>>>(z, cb);
    vq_resolve_kernel<<<32, 256>>>();
    vq_epilogue_kernel<<<EP_NCTA, EP_THREADS, EP_SMEM>>>(z, cb, out, out_size);
    vq_finalize_kernel<<<1, 256>>>(out, out_size);
}

// round 12
// speedup vs baseline: 1.4968x; 1.1311x over previous
#include <cuda_runtime.h>
#include <cuda_fp16.h>
#include <float.h>
#include <stdint.h>

// ============================ problem constants ============================
#define KCODES   4096
#define DIMS     256
#define NROWS    32768
#define ZELEMS   8388608
#define LOSS_OFF 8388608
#define IDX_OFF  8388609

// ============================ main GEMM config (R5/R9 geometry, frozen) ====
#define MT          128                  // z rows per CTA
#define NMMACTA     (NROWS / MT)         // 256 CTAs
#define NCODE       128                  // codes per chunk
#define NCHUNKS     (KCODES / NCODE)     // 32
#define DELTA       3.0e-4f              // provable-argmin margin (fp16 approx)

#define ROW_BYTES   528                  // 256 fp16 + 16B pad (LDSM conflict-free)
#define TILE_BYTES  (128 * ROW_BYTES)    // 67584 per A / B buffer
#define SM_A        0
#define SM_B0       TILE_BYTES
#define SM_B1       (2 * TILE_BYTES)
#define SM_MRG      (3 * TILE_BYTES)     // 2*512 floats + 512 ints = 6144
#define SM_TOTAL    (3 * TILE_BYTES + 6144)   // 208896 bytes

// fallback: 32-row batches x 256-code chunks, 64-code smem stages
#define FB_ROWS   32
#define FB_CODES  256
#define FB_CHUNKS (KCODES / FB_CODES)    // 16
#define FB_STAGE  64
#define FB_NSTAGE (FB_CODES / FB_STAGE)  // 4
#define FB_CBS_FLOATS (FB_STAGE * 257)   // 16448
#define FB_SMEM  ((FB_CBS_FLOATS + FB_ROWS * 256 + FB_ROWS) * 4 + FB_ROWS * 4)

// epilogue kernel tiling (validated R9)
#define EP_ROWS   64
#define EP_NCTA   (NROWS / EP_ROWS)      // 512
#define EP_THREADS 256
#define EP_STRIDE 260                    // floats; multiple of 4 -> aligned float4
#define EP_SMEM   (EP_ROWS * EP_STRIDE * 4)   // 66560 bytes dynamic

// ============================ device globals ===============================
__device__ float  g_esq[KCODES];
__device__ int    g_idx[NROWS];
__device__ double g_partials[EP_NCTA];
__device__ __align__(16) __half g_cbh[KCODES * DIMS];      // codebook fp16
__device__ int g_ucount;
__device__ int g_ulist[NROWS];
__device__ unsigned long long g_best[NROWS];               // packed (dist,k)

// ============================ PTX helpers ==================================
__device__ __forceinline__ uint32_t smem_u32(const void* p) {
    uint32_t a;
    asm("{ .reg .u64 t; cvta.to.shared.u64 t, %1; cvt.u32.u64 %0, t; }"
        : "=r"(a) : "l"(p));
    return a;
}

#define CP_ASYNC16(dst, src) \
    asm volatile("cp.async.cg.shared.global [%0], [%1], 16;" \
                 :: "r"(dst), "l"(src) : "memory")
#define CP_COMMIT() asm volatile("cp.async.commit_group;" ::: "memory")
#define CP_WAIT(n)  asm volatile("cp.async.wait_group %0;" :: "n"(n) : "memory")

#define LDSM_X4(r0, r1, r2, r3, addr) \
    asm volatile("ldmatrix.sync.aligned.m8n8.x4.shared.b16 {%0,%1,%2,%3}, [%4];" \
                 : "=r"(r0), "=r"(r1), "=r"(r2), "=r"(r3) : "r"(addr))

#define MMA_F16(acc, a, b0, b1) \
    asm volatile("mma.sync.aligned.m16n8k16.row.col.f32.f16.f16.f32 " \
        "{%0,%1,%2,%3}, {%4,%5,%6,%7}, {%8,%9}, {%0,%1,%2,%3};" \
        : "+f"((acc)[0]), "+f"((acc)[1]), "+f"((acc)[2]), "+f"((acc)[3]) \
        : "r"((a)[0]), "r"((a)[1]), "r"((a)[2]), "r"((a)[3]), \
          "r"(b0), "r"(b1))

__device__ __forceinline__ uint32_t pack_f16x2(float a0, float a1) {
    __half2 h2 = __floats2half2_rn(a0, a1);
    return *reinterpret_cast<uint32_t*>(&h2);
}

// ============== kernel 0: cb -> fp16 + e_sq + counter reset (merged) =======
__global__ void vq_cbprep(const float* __restrict__ cb) {
    const int warp = blockIdx.x * 8 + (threadIdx.x >> 5);
    const int lane = threadIdx.x & 31;
    if (blockIdx.x == 0 && threadIdx.x == 0) g_ucount = 0;
    if (warp >= KCODES) return;
    const float4* row = reinterpret_cast<const float4*>(cb) + (size_t)warp * 64;
    float4 v0 = row[lane];
    float4 v1 = row[lane + 32];
    float s = 0.0f;
    s = fmaf(v0.x, v0.x, s); s = fmaf(v0.y, v0.y, s);
    s = fmaf(v0.z, v0.z, s); s = fmaf(v0.w, v0.w, s);
    s = fmaf(v1.x, v1.x, s); s = fmaf(v1.y, v1.y, s);
    s = fmaf(v1.z, v1.z, s); s = fmaf(v1.w, v1.w, s);
    uint2 p0, p1;
    p0.x = pack_f16x2(v0.x, v0.y); p0.y = pack_f16x2(v0.z, v0.w);
    p1.x = pack_f16x2(v1.x, v1.y); p1.y = pack_f16x2(v1.z, v1.w);
    uint2* dst = reinterpret_cast<uint2*>(g_cbh + (size_t)warp * DIMS);
    dst[lane]      = p0;
    dst[lane + 32] = p1;
    #pragma unroll
    for (int o = 16; o > 0; o >>= 1) s += __shfl_down_sync(0xffffffffu, s, o);
    if (lane == 0) g_esq[warp] = s;
}

// ============================ kernel 1: HMMA GEMM + margin argmin ==========
// R5/R9 geometry; A (z) converted fp32->fp16 in-kernel (R6-validated math).
__global__ void __launch_bounds__(256, 1)
vq_mma_kernel(const float* __restrict__ z) {
    extern __shared__ char sm[];
    const uint32_t smb = smem_u32(sm);
    const int tid  = threadIdx.x;
    const int lane = tid & 31;
    const int w    = tid >> 5;
    const int mw   = w & 1;
    const int nw   = w >> 1;
    const int n0   = blockIdx.x * MT;
    const int b    = n0 >> 10;
    const int hw0  = n0 & 1023;

    // ---- stage B chunk 0 first (async), then convert A while B streams ----
    {
        const char* srcB = (const char*)g_cbh;
        #pragma unroll
        for (int i = 0; i < 16; ++i) {
            int seg = tid + i * 256;
            int rc = seg >> 5, s = seg & 31;
            CP_ASYNC16(smb + SM_B0 + rc * ROW_BYTES + s * 16,
                       srcB + (size_t)rc * 512 + s * 16);
        }
        CP_COMMIT();
    }
    // ---- stage A: z fp32 -> fp16 row-major in smem (replaces zprep pass) ---
    {
        const int r   = tid & 127;
        const int seg = tid >> 7;                // 0..1, 128 d's each
        const float* zp = z + ((size_t)b * 256 + seg * 128) * 1024 + hw0 + r;
        #pragma unroll
        for (int i = 0; i < 16; ++i) {
            uint4 q;
            uint32_t* qs = reinterpret_cast<uint32_t*>(&q);
            #pragma unroll
            for (int j = 0; j < 4; ++j) {
                float a0 = zp[(size_t)(i * 8 + 2 * j) * 1024];
                float a1 = zp[(size_t)(i * 8 + 2 * j + 1) * 1024];
                qs[j] = pack_f16x2(a0, a1);
            }
            *reinterpret_cast<uint4*>(sm + SM_A + r * ROW_BYTES
                                      + seg * 256 + i * 16) = q;
        }
    }

    const uint32_t lr = (uint32_t)((lane & 7) + ((lane >> 3) & 1) * 8);
    const uint32_t ch = (uint32_t)((lane >> 4) & 1);
    const uint32_t a_base = smb + SM_A + (mw * 64 + lr) * ROW_BYTES + ch * 16;
    const uint32_t b_off  = (nw * 32 + lr) * ROW_BYTES + ch * 16;

    float v1[8], v2[8]; int i1[8];
    #pragma unroll
    for (int r = 0; r < 8; ++r) { v1[r] = FLT_MAX; v2[r] = FLT_MAX; i1[r] = 0; }

    for (int c = 0; c < NCHUNKS; ++c) {
        if (c < NCHUNKS - 1) {
            const char* srcB = (const char*)g_cbh + (size_t)(c + 1) * NCODE * 512;
            uint32_t dstB = smb + (((c + 1) & 1) ? SM_B1 : SM_B0);
            #pragma unroll
            for (int i = 0; i < 16; ++i) {
                int seg = tid + i * 256;
                int rc = seg >> 5, s = seg & 31;
                CP_ASYNC16(dstB + rc * ROW_BYTES + s * 16,
                           srcB + (size_t)rc * 512 + s * 16);
            }
            CP_COMMIT();
            CP_WAIT(1);
        } else {
            CP_WAIT(0);
        }
        __syncthreads();

        const uint32_t bbuf = smb + ((c & 1) ? SM_B1 : SM_B0);

        float acc[4][4][4];
        #pragma unroll
        for (int mf = 0; mf < 4; ++mf)
            #pragma unroll
            for (int nf = 0; nf < 4; ++nf)
                #pragma unroll
                for (int i = 0; i < 4; ++i) acc[mf][nf][i] = 0.0f;

        #pragma unroll 4
        for (int ks = 0; ks < 16; ++ks) {
            uint32_t a[4][4];
            #pragma unroll
            for (int mf = 0; mf < 4; ++mf)
                LDSM_X4(a[mf][0], a[mf][1], a[mf][2], a[mf][3],
                        a_base + mf * (16 * ROW_BYTES) + ks * 32);
            uint32_t bf[2][4];
            #pragma unroll
            for (int p = 0; p < 2; ++p)
                LDSM_X4(bf[p][0], bf[p][1], bf[p][2], bf[p][3],
                        bbuf + b_off + p * (16 * ROW_BYTES) + ks * 32);
            #pragma unroll
            for (int mf = 0; mf < 4; ++mf) {
                #pragma unroll
                for (int p = 0; p < 2; ++p) {
                    MMA_F16(acc[mf][p * 2 + 0], a[mf], bf[p][0], bf[p][2]);
                    MMA_F16(acc[mf][p * 2 + 1], a[mf], bf[p][1], bf[p][3]);
                }
            }
        }

        // ---- shifted dists + running (best, second-best) ----
        const int kbase = c * NCODE + nw * 32;
        #pragma unroll
        for (int nf = 0; nf < 4; ++nf) {
            int kc = kbase + nf * 8 + (lane & 3) * 2;
            float2 e2 = *reinterpret_cast<const float2*>(&g_esq[kc]);
            #pragma unroll
            for (int mf = 0; mf < 4; ++mf) {
                #pragma unroll
                for (int i = 0; i < 4; ++i) {
                    int ri = mf * 2 + (i >> 1);
                    float e = (i & 1) ? e2.y : e2.x;
                    float d = fmaf(-2.0f, acc[mf][nf][i], e);
                    if (d < v2[ri]) {
                        if (d < v1[ri]) {
                            v2[ri] = v1[ri]; v1[ri] = d; i1[ri] = kc + (i & 1);
                        } else v2[ri] = d;
                    }
                }
            }
        }
        __syncthreads();
    }

    // ---- merge across the 4 lanes of each quad ----
    #pragma unroll
    for (int r = 0; r < 8; ++r) {
        #pragma unroll
        for (int off = 1; off < 4; off <<= 1) {
            float ov1 = __shfl_xor_sync(0xffffffffu, v1[r], off);
            float ov2 = __shfl_xor_sync(0xffffffffu, v2[r], off);
            int   oi  = __shfl_xor_sync(0xffffffffu, i1[r], off);
            float lo = fminf(v1[r], ov1);
            float hi = fmaxf(v1[r], ov1);
            float s2 = fminf(fminf(v2[r], ov2), hi);
            if (ov1 < v1[r] || (ov1 == v1[r] && oi < i1[r])) i1[r] = oi;
            v1[r] = lo; v2[r] = s2;
        }
    }

    // ---- cross-warp merge via smem, margin test ----
    float* mv1 = reinterpret_cast<float*>(sm + SM_MRG);
    float* mv2 = mv1 + 512;
    int*   mi  = reinterpret_cast<int*>(mv2 + 512);
    if ((lane & 3) == 0) {
        int q = lane >> 2;
        #pragma unroll
        for (int mf = 0; mf < 4; ++mf)
            #pragma unroll
            for (int dlt = 0; dlt < 2; ++dlt) {
                int row = mw * 64 + mf * 16 + dlt * 8 + q;
                int r = mf * 2 + dlt;
                mv1[nw * 128 + row] = v1[r];
                mv2[nw * 128 + row] = v2[r];
                mi [nw * 128 + row] = i1[r];
            }
    }
    __syncthreads();
    if (tid < 128) {
        float bv1 = mv1[tid], bv2 = mv2[tid];
        int   bi  = mi[tid];
        #pragma unroll
        for (int g = 1; g < 4; ++g) {
            float ov1 = mv1[g * 128 + tid], ov2 = mv2[g * 128 + tid];
            int   oi  = mi[g * 128 + tid];
            float lo = fminf(bv1, ov1);
            float hi = fmaxf(bv1, ov1);
            bv2 = fminf(fminf(bv2, ov2), hi);
            if (ov1 < bv1 || (ov1 == bv1 && oi < bi)) bi = oi;
            bv1 = lo;
        }
        int n = n0 + tid;
        if (__fsub_rn(bv2, bv1) > DELTA) {
            g_idx[n] = bi;                      // provably the reference argmin
        } else {
            g_best[n] = ~0ull;                  // init packed-min slot
            int p = atomicAdd(&g_ucount, 1);    // near-tie -> exact rescore
            g_ulist[p] = n;
        }
    }
}

// ============================ kernel 2: exact fallback (smem-staged) =======
// Task = (32-row batch) x (256-code chunk); 4 stages of 64 codes staged into
// smem coalescedly (stride-257 -> conflict-free scalar LDS). Per-(row,code)
// arithmetic identical to the validated fallback: same zsq shuffle tree,
// sequential-d per-thread fmaf dot, fl(fl(zsq-2dot)+esq). Merge: warp min
// then atomicMin on packed (dist_bits<<32)|k (order-independent).
__global__ void __launch_bounds__(512)
vq_fallback_kernel(const float* __restrict__ z, const float* __restrict__ cb) {
    extern __shared__ float fsm[];
    float* cbs  = fsm;                            // [64 * 257]
    float* zrow = fsm + FB_CBS_FLOATS;            // [32][256]
    float* zsqs = zrow + FB_ROWS * 256;           // [32]
    int*   rown = reinterpret_cast<int*>(zsqs + FB_ROWS);   // [32]

    const int t = threadIdx.x;
    const int cnt = g_ucount;
    const int nbatch = (cnt + FB_ROWS - 1) / FB_ROWS;
    const int ntasks = nbatch * FB_CHUNKS;

    for (int task = blockIdx.x; task < ntasks; task += gridDim.x) {
        const int batch = task >> 4;              // FB_CHUNKS = 16
        const int chunk = task & 15;
        const int base  = batch * FB_ROWS;
        const int nr    = min(FB_ROWS, cnt - base);

        __syncthreads();                          // protect smem reuse
        if (t < FB_ROWS) rown[t] = g_ulist[base + min(t, nr - 1)];
        __syncthreads();
        for (int e = t; e < FB_ROWS * 256; e += 512) {
            int j = e >> 8, d = e & 255;
            int n = rown[j], bb = n >> 10, hw = n & 1023;
            zrow[j * 256 + d] = z[((size_t)bb * 256 + d) * 1024 + hw];
        }
        __syncthreads();
        // zsq per row (validated shuffle-tree order)
        {
            int wj = t >> 5, lane = t & 31;
            for (int rr = wj; rr < FB_ROWS; rr += 16) {
                float s = 0.0f;
                #pragma unroll
                for (int j = 0; j < 8; ++j) {
                    float v = zrow[rr * 256 + lane + 32 * j];
                    s = fmaf(v, v, s);
                }
                #pragma unroll
                for (int o = 16; o > 0; o >>= 1) s += __shfl_down_sync(0xffffffffu, s, o);
                if (lane == 0) zsqs[rr] = s;
            }
        }
        __syncthreads();

        const int c    = t & 63;
        const int slot = t >> 6;                  // rows slot*4 .. slot*4+3
        const int j0   = slot * 4;

        for (int st = 0; st < FB_NSTAGE; ++st) {
            const int k0 = chunk * FB_CODES + st * FB_STAGE;
            // stage 64 code rows coalescedly
            const float4* cb4 = reinterpret_cast<const float4*>(cb);
            #pragma unroll
            for (int ii = 0; ii < 8; ++ii) {
                int idx = t + ii * 512;           // 0..4095
                int row = idx >> 6, q = idx & 63;
                float4 v = cb4[(size_t)(k0 + row) * 64 + q];
                float* dstp = &cbs[row * 257 + q * 4];
                dstp[0] = v.x; dstp[1] = v.y; dstp[2] = v.z; dstp[3] = v.w;
            }
            __syncthreads();

            float dot0 = 0.0f, dot1 = 0.0f, dot2 = 0.0f, dot3 = 0.0f;
            const float* cc = &cbs[c * 257];
            const float* z0 = &zrow[(j0 + 0) * 256];
            const float* z1 = &zrow[(j0 + 1) * 256];
            const float* z2 = &zrow[(j0 + 2) * 256];
            const float* z3 = &zrow[(j0 + 3) * 256];
            #pragma unroll 8
            for (int d = 0; d < 256; ++d) {
                float e = cc[d];
                dot0 = fmaf(z0[d], e, dot0);
                dot1 = fmaf(z1[d], e, dot1);
                dot2 = fmaf(z2[d], e, dot2);
                dot3 = fmaf(z3[d], e, dot3);
            }
            const int k = k0 + c;
            const float es = g_esq[k];
            float dist[4];
            dist[0] = __fadd_rn(__fsub_rn(zsqs[j0 + 0], __fmul_rn(2.0f, dot0)), es);
            dist[1] = __fadd_rn(__fsub_rn(zsqs[j0 + 1], __fmul_rn(2.0f, dot1)), es);
            dist[2] = __fadd_rn(__fsub_rn(zsqs[j0 + 2], __fmul_rn(2.0f, dot2)), es);
            dist[3] = __fadd_rn(__fsub_rn(zsqs[j0 + 3], __fmul_rn(2.0f, dot3)), es);
            #pragma unroll
            for (int j = 0; j < 4; ++j) {
                unsigned long long p =
                    ((unsigned long long)__float_as_uint(dist[j]) << 32) | (unsigned)k;
                #pragma unroll
                for (int o = 16; o > 0; o >>= 1) {
                    unsigned long long op = __shfl_xor_sync(0xffffffffu, p, o);
                    if (op < p) p = op;
                }
                if ((t & 31) == 0 && (j0 + j) < nr)
                    atomicMin(&g_best[rown[j0 + j]], p);
            }
            __syncthreads();
        }
    }
}

// ============================ kernel 2b: resolve packed minima =============
__global__ void vq_resolve_kernel() {
    const int cnt = g_ucount;
    for (int i = blockIdx.x * blockDim.x + threadIdx.x; i < cnt;
         i += gridDim.x * blockDim.x) {
        int n = g_ulist[i];
        g_idx[n] = (int)(g_best[n] & 0xffffffffu);
    }
}

// ============================ kernel 3: output epilogue (two-phase, R9) ====
__global__ void __launch_bounds__(EP_THREADS)
vq_epilogue_kernel(const float* __restrict__ z, const float* __restrict__ cb,
                   float* __restrict__ out, int out_size) {
    extern __shared__ float zq[];                 // [64][EP_STRIDE]
    __shared__ int idx_s[EP_ROWS];
    __shared__ double red[EP_THREADS];

    const int t  = threadIdx.x;
    const int n0 = blockIdx.x * EP_ROWS;

    if (t < EP_ROWS) {
        int ii = g_idx[n0 + t];
        idx_s[t] = ii;
        int oi = IDX_OFF + n0 + t;
        if (oi < out_size) out[oi] = (float)ii;
    }
    __syncthreads();

    {
        const int wj   = t >> 5;
        const int lane = t & 31;
        #pragma unroll
        for (int rr = 0; rr < 8; ++rr) {
            int row = wj * 8 + rr;
            const float4* src = reinterpret_cast<const float4*>(
                cb + (size_t)idx_s[row] * DIMS);
            float4 q0 = src[lane];
            float4 q1 = src[lane + 32];
            float* dst = &zq[row * EP_STRIDE];
            *reinterpret_cast<float4*>(dst + lane * 4)       = q0;
            *reinterpret_cast<float4*>(dst + 128 + lane * 4) = q1;
        }
    }
    __syncthreads();

    const int b   = n0 >> 10;
    const int hw0 = n0 & 1023;
    const float* zb = z + ((size_t)b * 256) * 1024 + hw0;
    float*       ob = out + ((size_t)b * 256) * 1024 + hw0;

    const int r  = t & 63;
    const int dq = t >> 6;
    const float* qrow = &zq[r * EP_STRIDE];

    double accd = 0.0;
    #pragma unroll 8
    for (int p = 0; p < 64; ++p) {
        int d = dq * 64 + p;
        float qv = qrow[d];
        float zv = zb[(size_t)d * 1024 + r];
        float diff = __fsub_rn(qv, zv);
        ob[(size_t)d * 1024 + r] = __fadd_rn(zv, diff);   // straight-through
        accd = fma((double)diff, (double)diff, accd);
    }

    red[t] = accd;
    __syncthreads();
    for (int s = EP_THREADS / 2; s > 0; s >>= 1) {
        if (t < s) red[t] += red[t + s];
        __syncthreads();
    }
    if (t == 0) g_partials[blockIdx.x] = red[0];
}

// ============================ kernel 4: finalize loss ======================
__global__ void vq_finalize_kernel(float* __restrict__ out, int out_size) {
    __shared__ double red[256];
    const int t = threadIdx.x;
    red[t] = g_partials[t] + g_partials[t + 256];
    __syncthreads();
    for (int s = 128; s > 0; s >>= 1) {
        if (t < s) red[t] += red[t + s];
        __syncthreads();
    }
    if (t == 0 && LOSS_OFF < out_size) {
        double mean = red[0] / (double)ZELEMS;
        float m = (float)mean;
        out[LOSS_OFF] = __fadd_rn(m, __fmul_rn(0.25f, m));
    }
}

// ============================ launch ======================================
extern "C" void kernel_launch(void* const* d_in, const int* in_sizes, int n_in,
                              void* d_out, int out_size) {
    const float* z  = (const float*)d_in[0];
    const float* cb = (const float*)d_in[1];
    if (n_in >= 2 && in_sizes[0] == KCODES * DIMS && in_sizes[1] == ZELEMS) {
        const float* tmp = z; z = cb; cb = tmp;
    }
    float* out = (float*)d_out;

    cudaFuncSetAttribute(vq_mma_kernel,
                         cudaFuncAttributeMaxDynamicSharedMemorySize, SM_TOTAL);
    cudaFuncSetAttribute(vq_fallback_kernel,
                         cudaFuncAttributeMaxDynamicSharedMemorySize, FB_SMEM);
    cudaFuncSetAttribute(vq_epilogue_kernel,
                         cudaFuncAttributeMaxDynamicSharedMemorySize, EP_SMEM);

    vq_cbprep<<<KCODES / 8, 256>>>(cb);
    vq_mma_kernel<<<NMMACTA, 256, SM_TOTAL>>>(z);
    vq_fallback_kernel<<<512, 512, FB_SMEM>>>(z, cb);
    vq_resolve_kernel<<<32, 256>>>();
    vq_epilogue_kernel<<<EP_NCTA, EP_THREADS, EP_SMEM>>>(z, cb, out, out_size);
    vq_finalize_kernel<<<1, 256>>>(out, out_size);
}

// round 13
// speedup vs baseline: 1.5371x; 1.0270x over previous
#include <cuda_runtime.h>
#include <cuda_fp16.h>
#include <float.h>
#include <stdint.h>

// ============================ problem constants ============================
#define KCODES   4096
#define DIMS     256
#define NROWS    32768
#define ZELEMS   8388608
#define LOSS_OFF 8388608
#define IDX_OFF  8388609

// ============================ main GEMM config (R5/R9 geometry, frozen) ====
#define MT          128                  // z rows per CTA
#define NMMACTA     (NROWS / MT)         // 256 CTAs
#define NCODE       128                  // codes per chunk
#define NCHUNKS     (KCODES / NCODE)     // 32
#define DELTA       3.0e-4f              // provable-argmin margin (fp16 approx)

#define ROW_BYTES   528                  // 256 fp16 + 16B pad (LDSM conflict-free)
#define TILE_BYTES  (128 * ROW_BYTES)    // 67584 per A / B buffer
#define SM_A        0
#define SM_B0       TILE_BYTES
#define SM_B1       (2 * TILE_BYTES)
#define SM_MRG      (3 * TILE_BYTES)     // 2*512 floats + 512 ints = 6144
#define SM_TOTAL    (3 * TILE_BYTES + 6144)   // 208896 bytes

// fallback: 32-row batches x 256-code chunks, 64-code smem stages (R12)
#define FB_ROWS   32
#define FB_CODES  256
#define FB_CHUNKS (KCODES / FB_CODES)    // 16
#define FB_STAGE  64
#define FB_NSTAGE (FB_CODES / FB_STAGE)  // 4
#define FB_CBS_FLOATS (FB_STAGE * 257)   // 16448
#define FB_SMEM  ((FB_CBS_FLOATS + FB_ROWS * 256 + FB_ROWS) * 4 + FB_ROWS * 4)

// epilogue kernel tiling (validated R9)
#define EP_ROWS   64
#define EP_NCTA   (NROWS / EP_ROWS)      // 512
#define EP_THREADS 256
#define EP_STRIDE 260                    // floats; multiple of 4 -> aligned float4
#define EP_SMEM   (EP_ROWS * EP_STRIDE * 4)   // 66560 bytes dynamic

// ============================ device globals ===============================
__device__ float  g_esq[KCODES];
__device__ int    g_idx[NROWS];
__device__ double g_partials[EP_NCTA];
__device__ __align__(16) __half g_cbh[KCODES * DIMS];      // codebook fp16
__device__ int g_ucount;
__device__ int g_ulist[NROWS];
__device__ unsigned long long g_best[NROWS];               // packed (dist,k)

// ============================ PTX helpers ==================================
__device__ __forceinline__ uint32_t smem_u32(const void* p) {
    uint32_t a;
    asm("{ .reg .u64 t; cvta.to.shared.u64 t, %1; cvt.u32.u64 %0, t; }"
        : "=r"(a) : "l"(p));
    return a;
}

#define CP_ASYNC16(dst, src) \
    asm volatile("cp.async.cg.shared.global [%0], [%1], 16;" \
                 :: "r"(dst), "l"(src) : "memory")
#define CP_COMMIT() asm volatile("cp.async.commit_group;" ::: "memory")
#define CP_WAIT(n)  asm volatile("cp.async.wait_group %0;" :: "n"(n) : "memory")

#define LDSM_X4(r0, r1, r2, r3, addr) \
    asm volatile("ldmatrix.sync.aligned.m8n8.x4.shared.b16 {%0,%1,%2,%3}, [%4];" \
                 : "=r"(r0), "=r"(r1), "=r"(r2), "=r"(r3) : "r"(addr))

#define MMA_F16(acc, a, b0, b1) \
    asm volatile("mma.sync.aligned.m16n8k16.row.col.f32.f16.f16.f32 " \
        "{%0,%1,%2,%3}, {%4,%5,%6,%7}, {%8,%9}, {%0,%1,%2,%3};" \
        : "+f"((acc)[0]), "+f"((acc)[1]), "+f"((acc)[2]), "+f"((acc)[3]) \
        : "r"((a)[0]), "r"((a)[1]), "r"((a)[2]), "r"((a)[3]), \
          "r"(b0), "r"(b1))

__device__ __forceinline__ uint32_t pack_f16x2(float a0, float a1) {
    __half2 h2 = __floats2half2_rn(a0, a1);
    return *reinterpret_cast<uint32_t*>(&h2);
}

// ============== kernel 0a: cb -> fp16 + e_sq + counter reset (merged) ======
__global__ void vq_cbprep(const float* __restrict__ cb) {
    const int warp = blockIdx.x * 8 + (threadIdx.x >> 5);
    const int lane = threadIdx.x & 31;
    if (blockIdx.x == 0 && threadIdx.x == 0) g_ucount = 0;
    if (warp >= KCODES) return;
    const float4* row = reinterpret_cast<const float4*>(cb) + (size_t)warp * 64;
    float4 v0 = row[lane];
    float4 v1 = row[lane + 32];
    float s = 0.0f;
    s = fmaf(v0.x, v0.x, s); s = fmaf(v0.y, v0.y, s);
    s = fmaf(v0.z, v0.z, s); s = fmaf(v0.w, v0.w, s);
    s = fmaf(v1.x, v1.x, s); s = fmaf(v1.y, v1.y, s);
    s = fmaf(v1.z, v1.z, s); s = fmaf(v1.w, v1.w, s);
    uint2 p0, p1;
    p0.x = pack_f16x2(v0.x, v0.y); p0.y = pack_f16x2(v0.z, v0.w);
    p1.x = pack_f16x2(v1.x, v1.y); p1.y = pack_f16x2(v1.z, v1.w);
    uint2* dst = reinterpret_cast<uint2*>(g_cbh + (size_t)warp * DIMS);
    dst[lane]      = p0;
    dst[lane + 32] = p1;
    #pragma unroll
    for (int o = 16; o > 0; o >>= 1) s += __shfl_down_sync(0xffffffffu, s, o);
    if (lane == 0) g_esq[warp] = s;
}

// ====== kernels 0b/0c: tiny spacers so vq_mma is the 4th launch (ncu) ======
__global__ void vq_spacer_a() {
    if (blockIdx.x == 0 && threadIdx.x == 0) g_ucount = 0;  // re-zero, harmless
}
__global__ void vq_spacer_b() {
    if (blockIdx.x == 0 && threadIdx.x == 0 && g_ucount > NROWS) g_ucount = 0;
}

// ============================ kernel 1: HMMA GEMM + margin argmin ==========
// R5/R9 geometry; A (z) converted fp32->fp16 in-kernel. ks loop fully
// unrolled: 256 regs/thread available at 1 CTA x 256 thr -> let ptxas
// software-pipeline LDSM several stages ahead of the MMAs.
__global__ void __launch_bounds__(256, 1)
vq_mma_kernel(const float* __restrict__ z) {
    extern __shared__ char sm[];
    const uint32_t smb = smem_u32(sm);
    const int tid  = threadIdx.x;
    const int lane = tid & 31;
    const int w    = tid >> 5;
    const int mw   = w & 1;
    const int nw   = w >> 1;
    const int n0   = blockIdx.x * MT;
    const int b    = n0 >> 10;
    const int hw0  = n0 & 1023;

    // ---- stage B chunk 0 first (async), then convert A while B streams ----
    {
        const char* srcB = (const char*)g_cbh;
        #pragma unroll
        for (int i = 0; i < 16; ++i) {
            int seg = tid + i * 256;
            int rc = seg >> 5, s = seg & 31;
            CP_ASYNC16(smb + SM_B0 + rc * ROW_BYTES + s * 16,
                       srcB + (size_t)rc * 512 + s * 16);
        }
        CP_COMMIT();
    }
    // ---- stage A: z fp32 -> fp16 row-major in smem (replaces zprep pass) ---
    {
        const int r   = tid & 127;
        const int seg = tid >> 7;                // 0..1, 128 d's each
        const float* zp = z + ((size_t)b * 256 + seg * 128) * 1024 + hw0 + r;
        #pragma unroll
        for (int i = 0; i < 16; ++i) {
            uint4 q;
            uint32_t* qs = reinterpret_cast<uint32_t*>(&q);
            #pragma unroll
            for (int j = 0; j < 4; ++j) {
                float a0 = zp[(size_t)(i * 8 + 2 * j) * 1024];
                float a1 = zp[(size_t)(i * 8 + 2 * j + 1) * 1024];
                qs[j] = pack_f16x2(a0, a1);
            }
            *reinterpret_cast<uint4*>(sm + SM_A + r * ROW_BYTES
                                      + seg * 256 + i * 16) = q;
        }
    }

    const uint32_t lr = (uint32_t)((lane & 7) + ((lane >> 3) & 1) * 8);
    const uint32_t ch = (uint32_t)((lane >> 4) & 1);
    const uint32_t a_base = smb + SM_A + (mw * 64 + lr) * ROW_BYTES + ch * 16;
    const uint32_t b_off  = (nw * 32 + lr) * ROW_BYTES + ch * 16;

    float v1[8], v2[8]; int i1[8];
    #pragma unroll
    for (int r = 0; r < 8; ++r) { v1[r] = FLT_MAX; v2[r] = FLT_MAX; i1[r] = 0; }

    for (int c = 0; c < NCHUNKS; ++c) {
        if (c < NCHUNKS - 1) {
            const char* srcB = (const char*)g_cbh + (size_t)(c + 1) * NCODE * 512;
            uint32_t dstB = smb + (((c + 1) & 1) ? SM_B1 : SM_B0);
            #pragma unroll
            for (int i = 0; i < 16; ++i) {
                int seg = tid + i * 256;
                int rc = seg >> 5, s = seg & 31;
                CP_ASYNC16(dstB + rc * ROW_BYTES + s * 16,
                           srcB + (size_t)rc * 512 + s * 16);
            }
            CP_COMMIT();
            CP_WAIT(1);
        } else {
            CP_WAIT(0);
        }
        __syncthreads();

        const uint32_t bbuf = smb + ((c & 1) ? SM_B1 : SM_B0);

        float acc[4][4][4];
        #pragma unroll
        for (int mf = 0; mf < 4; ++mf)
            #pragma unroll
            for (int nf = 0; nf < 4; ++nf)
                #pragma unroll
                for (int i = 0; i < 4; ++i) acc[mf][nf][i] = 0.0f;

        #pragma unroll
        for (int ks = 0; ks < 16; ++ks) {
            uint32_t a[4][4];
            #pragma unroll
            for (int mf = 0; mf < 4; ++mf)
                LDSM_X4(a[mf][0], a[mf][1], a[mf][2], a[mf][3],
                        a_base + mf * (16 * ROW_BYTES) + ks * 32);
            uint32_t bf[2][4];
            #pragma unroll
            for (int p = 0; p < 2; ++p)
                LDSM_X4(bf[p][0], bf[p][1], bf[p][2], bf[p][3],
                        bbuf + b_off + p * (16 * ROW_BYTES) + ks * 32);
            #pragma unroll
            for (int mf = 0; mf < 4; ++mf) {
                #pragma unroll
                for (int p = 0; p < 2; ++p) {
                    MMA_F16(acc[mf][p * 2 + 0], a[mf], bf[p][0], bf[p][2]);
                    MMA_F16(acc[mf][p * 2 + 1], a[mf], bf[p][1], bf[p][3]);
                }
            }
        }

        // ---- shifted dists + running (best, second-best) ----
        const int kbase = c * NCODE + nw * 32;
        #pragma unroll
        for (int nf = 0; nf < 4; ++nf) {
            int kc = kbase + nf * 8 + (lane & 3) * 2;
            float2 e2 = *reinterpret_cast<const float2*>(&g_esq[kc]);
            #pragma unroll
            for (int mf = 0; mf < 4; ++mf) {
                #pragma unroll
                for (int i = 0; i < 4; ++i) {
                    int ri = mf * 2 + (i >> 1);
                    float e = (i & 1) ? e2.y : e2.x;
                    float d = fmaf(-2.0f, acc[mf][nf][i], e);
                    if (d < v2[ri]) {
                        if (d < v1[ri]) {
                            v2[ri] = v1[ri]; v1[ri] = d; i1[ri] = kc + (i & 1);
                        } else v2[ri] = d;
                    }
                }
            }
        }
        __syncthreads();
    }

    // ---- merge across the 4 lanes of each quad ----
    #pragma unroll
    for (int r = 0; r < 8; ++r) {
        #pragma unroll
        for (int off = 1; off < 4; off <<= 1) {
            float ov1 = __shfl_xor_sync(0xffffffffu, v1[r], off);
            float ov2 = __shfl_xor_sync(0xffffffffu, v2[r], off);
            int   oi  = __shfl_xor_sync(0xffffffffu, i1[r], off);
            float lo = fminf(v1[r], ov1);
            float hi = fmaxf(v1[r], ov1);
            float s2 = fminf(fminf(v2[r], ov2), hi);
            if (ov1 < v1[r] || (ov1 == v1[r] && oi < i1[r])) i1[r] = oi;
            v1[r] = lo; v2[r] = s2;
        }
    }

    // ---- cross-warp merge via smem, margin test ----
    float* mv1 = reinterpret_cast<float*>(sm + SM_MRG);
    float* mv2 = mv1 + 512;
    int*   mi  = reinterpret_cast<int*>(mv2 + 512);
    if ((lane & 3) == 0) {
        int q = lane >> 2;
        #pragma unroll
        for (int mf = 0; mf < 4; ++mf)
            #pragma unroll
            for (int dlt = 0; dlt < 2; ++dlt) {
                int row = mw * 64 + mf * 16 + dlt * 8 + q;
                int r = mf * 2 + dlt;
                mv1[nw * 128 + row] = v1[r];
                mv2[nw * 128 + row] = v2[r];
                mi [nw * 128 + row] = i1[r];
            }
    }
    __syncthreads();
    if (tid < 128) {
        float bv1 = mv1[tid], bv2 = mv2[tid];
        int   bi  = mi[tid];
        #pragma unroll
        for (int g = 1; g < 4; ++g) {
            float ov1 = mv1[g * 128 + tid], ov2 = mv2[g * 128 + tid];
            int   oi  = mi[g * 128 + tid];
            float lo = fminf(bv1, ov1);
            float hi = fmaxf(bv1, ov1);
            bv2 = fminf(fminf(bv2, ov2), hi);
            if (ov1 < bv1 || (ov1 == bv1 && oi < bi)) bi = oi;
            bv1 = lo;
        }
        int n = n0 + tid;
        if (__fsub_rn(bv2, bv1) > DELTA) {
            g_idx[n] = bi;                      // provably the reference argmin
        } else {
            g_best[n] = ~0ull;                  // init packed-min slot
            int p = atomicAdd(&g_ucount, 1);    // near-tie -> exact rescore
            g_ulist[p] = n;
        }
    }
}

// ============================ kernel 2: exact fallback (smem-staged, R12) ==
__global__ void __launch_bounds__(512)
vq_fallback_kernel(const float* __restrict__ z, const float* __restrict__ cb) {
    extern __shared__ float fsm[];
    float* cbs  = fsm;                            // [64 * 257]
    float* zrow = fsm + FB_CBS_FLOATS;            // [32][256]
    float* zsqs = zrow + FB_ROWS * 256;           // [32]
    int*   rown = reinterpret_cast<int*>(zsqs + FB_ROWS);   // [32]

    const int t = threadIdx.x;
    const int cnt = g_ucount;
    const int nbatch = (cnt + FB_ROWS - 1) / FB_ROWS;
    const int ntasks = nbatch * FB_CHUNKS;

    for (int task = blockIdx.x; task < ntasks; task += gridDim.x) {
        const int batch = task >> 4;              // FB_CHUNKS = 16
        const int chunk = task & 15;
        const int base  = batch * FB_ROWS;
        const int nr    = min(FB_ROWS, cnt - base);

        __syncthreads();                          // protect smem reuse
        if (t < FB_ROWS) rown[t] = g_ulist[base + min(t, nr - 1)];
        __syncthreads();
        for (int e = t; e < FB_ROWS * 256; e += 512) {
            int j = e >> 8, d = e & 255;
            int n = rown[j], bb = n >> 10, hw = n & 1023;
            zrow[j * 256 + d] = z[((size_t)bb * 256 + d) * 1024 + hw];
        }
        __syncthreads();
        {
            int wj = t >> 5, lane = t & 31;
            for (int rr = wj; rr < FB_ROWS; rr += 16) {
                float s = 0.0f;
                #pragma unroll
                for (int j = 0; j < 8; ++j) {
                    float v = zrow[rr * 256 + lane + 32 * j];
                    s = fmaf(v, v, s);
                }
                #pragma unroll
                for (int o = 16; o > 0; o >>= 1) s += __shfl_down_sync(0xffffffffu, s, o);
                if (lane == 0) zsqs[rr] = s;
            }
        }
        __syncthreads();

        const int c    = t & 63;
        const int slot = t >> 6;                  // rows slot*4 .. slot*4+3
        const int j0   = slot * 4;

        for (int st = 0; st < FB_NSTAGE; ++st) {
            const int k0 = chunk * FB_CODES + st * FB_STAGE;
            const float4* cb4 = reinterpret_cast<const float4*>(cb);
            #pragma unroll
            for (int ii = 0; ii < 8; ++ii) {
                int idx = t + ii * 512;           // 0..4095
                int row = idx >> 6, q = idx & 63;
                float4 v = cb4[(size_t)(k0 + row) * 64 + q];
                float* dstp = &cbs[row * 257 + q * 4];
                dstp[0] = v.x; dstp[1] = v.y; dstp[2] = v.z; dstp[3] = v.w;
            }
            __syncthreads();

            float dot0 = 0.0f, dot1 = 0.0f, dot2 = 0.0f, dot3 = 0.0f;
            const float* cc = &cbs[c * 257];
            const float* z0 = &zrow[(j0 + 0) * 256];
            const float* z1 = &zrow[(j0 + 1) * 256];
            const float* z2 = &zrow[(j0 + 2) * 256];
            const float* z3 = &zrow[(j0 + 3) * 256];
            #pragma unroll 8
            for (int d = 0; d < 256; ++d) {
                float e = cc[d];
                dot0 = fmaf(z0[d], e, dot0);
                dot1 = fmaf(z1[d], e, dot1);
                dot2 = fmaf(z2[d], e, dot2);
                dot3 = fmaf(z3[d], e, dot3);
            }
            const int k = k0 + c;
            const float es = g_esq[k];
            float dist[4];
            dist[0] = __fadd_rn(__fsub_rn(zsqs[j0 + 0], __fmul_rn(2.0f, dot0)), es);
            dist[1] = __fadd_rn(__fsub_rn(zsqs[j0 + 1], __fmul_rn(2.0f, dot1)), es);
            dist[2] = __fadd_rn(__fsub_rn(zsqs[j0 + 2], __fmul_rn(2.0f, dot2)), es);
            dist[3] = __fadd_rn(__fsub_rn(zsqs[j0 + 3], __fmul_rn(2.0f, dot3)), es);
            #pragma unroll
            for (int j = 0; j < 4; ++j) {
                unsigned long long p =
                    ((unsigned long long)__float_as_uint(dist[j]) << 32) | (unsigned)k;
                #pragma unroll
                for (int o = 16; o > 0; o >>= 1) {
                    unsigned long long op = __shfl_xor_sync(0xffffffffu, p, o);
                    if (op < p) p = op;
                }
                if ((t & 31) == 0 && (j0 + j) < nr)
                    atomicMin(&g_best[rown[j0 + j]], p);
            }
            __syncthreads();
        }
    }
}

// ============================ kernel 2b: resolve packed minima =============
__global__ void vq_resolve_kernel() {
    const int cnt = g_ucount;
    for (int i = blockIdx.x * blockDim.x + threadIdx.x; i < cnt;
         i += gridDim.x * blockDim.x) {
        int n = g_ulist[i];
        g_idx[n] = (int)(g_best[n] & 0xffffffffu);
    }
}

// ============================ kernel 3: output epilogue (two-phase, R9) ====
__global__ void __launch_bounds__(EP_THREADS)
vq_epilogue_kernel(const float* __restrict__ z, const float* __restrict__ cb,
                   float* __restrict__ out, int out_size) {
    extern __shared__ float zq[];                 // [64][EP_STRIDE]
    __shared__ int idx_s[EP_ROWS];
    __shared__ double red[EP_THREADS];

    const int t  = threadIdx.x;
    const int n0 = blockIdx.x * EP_ROWS;

    if (t < EP_ROWS) {
        int ii = g_idx[n0 + t];
        idx_s[t] = ii;
        int oi = IDX_OFF + n0 + t;
        if (oi < out_size) out[oi] = (float)ii;
    }
    __syncthreads();

    {
        const int wj   = t >> 5;
        const int lane = t & 31;
        #pragma unroll
        for (int rr = 0; rr < 8; ++rr) {
            int row = wj * 8 + rr;
            const float4* src = reinterpret_cast<const float4*>(
                cb + (size_t)idx_s[row] * DIMS);
            float4 q0 = src[lane];
            float4 q1 = src[lane + 32];
            float* dst = &zq[row * EP_STRIDE];
            *reinterpret_cast<float4*>(dst + lane * 4)       = q0;
            *reinterpret_cast<float4*>(dst + 128 + lane * 4) = q1;
        }
    }
    __syncthreads();

    const int b   = n0 >> 10;
    const int hw0 = n0 & 1023;
    const float* zb = z + ((size_t)b * 256) * 1024 + hw0;
    float*       ob = out + ((size_t)b * 256) * 1024 + hw0;

    const int r  = t & 63;
    const int dq = t >> 6;
    const float* qrow = &zq[r * EP_STRIDE];

    double accd = 0.0;
    #pragma unroll 8
    for (int p = 0; p < 64; ++p) {
        int d = dq * 64 + p;
        float qv = qrow[d];
        float zv = zb[(size_t)d * 1024 + r];
        float diff = __fsub_rn(qv, zv);
        ob[(size_t)d * 1024 + r] = __fadd_rn(zv, diff);   // straight-through
        accd = fma((double)diff, (double)diff, accd);
    }

    red[t] = accd;
    __syncthreads();
    for (int s = EP_THREADS / 2; s > 0; s >>= 1) {
        if (t < s) red[t] += red[t + s];
        __syncthreads();
    }
    if (t == 0) g_partials[blockIdx.x] = red[0];
}

// ============================ kernel 4: finalize loss ======================
__global__ void vq_finalize_kernel(float* __restrict__ out, int out_size) {
    __shared__ double red[256];
    const int t = threadIdx.x;
    red[t] = g_partials[t] + g_partials[t + 256];
    __syncthreads();
    for (int s = 128; s > 0; s >>= 1) {
        if (t < s) red[t] += red[t + s];
        __syncthreads();
    }
    if (t == 0 && LOSS_OFF < out_size) {
        double mean = red[0] / (double)ZELEMS;
        float m = (float)mean;
        out[LOSS_OFF] = __fadd_rn(m, __fmul_rn(0.25f, m));
    }
}

// ============================ launch ======================================
extern "C" void kernel_launch(void* const* d_in, const int* in_sizes, int n_in,
                              void* d_out, int out_size) {
    const float* z  = (const float*)d_in[0];
    const float* cb = (const float*)d_in[1];
    if (n_in >= 2 && in_sizes[0] == KCODES * DIMS && in_sizes[1] == ZELEMS) {
        const float* tmp = z; z = cb; cb = tmp;
    }
    float* out = (float*)d_out;

    cudaFuncSetAttribute(vq_mma_kernel,
                         cudaFuncAttributeMaxDynamicSharedMemorySize, SM_TOTAL);
    cudaFuncSetAttribute(vq_fallback_kernel,
                         cudaFuncAttributeMaxDynamicSharedMemorySize, FB_SMEM);
    cudaFuncSetAttribute(vq_epilogue_kernel,
                         cudaFuncAttributeMaxDynamicSharedMemorySize, EP_SMEM);

    vq_cbprep<<<KCODES / 8, 256>>>(cb);
    vq_spacer_a<<<1, 32>>>();                 // spacers: make vq_mma launch #4
    vq_spacer_b<<<1, 32>>>();                 // (ncu profiles the 4th launch)
    vq_mma_kernel<<<NMMACTA, 256, SM_TOTAL>>>(z);
    vq_fallback_kernel<<<512, 512, FB_SMEM>>>(z, cb);
    vq_resolve_kernel<<<32, 256>>>();
    vq_epilogue_kernel<<<EP_NCTA, EP_THREADS, EP_SMEM>>>(z, cb, out, out_size);
    vq_finalize_kernel<<<1, 256>>>(out, out_size);
}